// round 2
// baseline (speedup 1.0000x reference)
#include <cuda_runtime.h>

#define BQ 64
#define TT 256
#define HU 1024
#define HD 512
#define NG 4096

// Scratch (static device arrays: allocation-free per harness rules)
__device__ float g_Gpre[(long long)TT * BQ * NG];  // 256 MiB precomputed input gates (+biases)
__device__ float g_h0[2][BQ * HU];
__device__ float g_h1[2][BQ * HU];
__device__ float g_c0[BQ * HU];
__device__ float g_c1[BQ * HU];

__device__ __forceinline__ unsigned f2tf(float f) {
    unsigned r;
    asm("cvt.rna.tf32.f32 %0, %1;" : "=r"(r) : "f"(f));
    return r;
}

__device__ __forceinline__ void mma8(float* c, const unsigned* a, const unsigned* b) {
    asm volatile(
        "mma.sync.aligned.m16n8k8.row.col.f32.tf32.tf32.f32 "
        "{%0,%1,%2,%3}, {%4,%5,%6,%7}, {%8,%9}, {%0,%1,%2,%3};\n"
        : "+f"(c[0]), "+f"(c[1]), "+f"(c[2]), "+f"(c[3])
        : "r"(a[0]), "r"(a[1]), "r"(a[2]), "r"(a[3]), "r"(b[0]), "r"(b[1]));
}

// ---------------------------------------------------------------------------
// Zero initial states
// ---------------------------------------------------------------------------
__global__ void zero_kernel() {
    int i = blockIdx.x * blockDim.x + threadIdx.x;
    if (i < BQ * HU) {
        g_h0[0][i] = 0.f; g_h0[1][i] = 0.f;
        g_h1[0][i] = 0.f; g_h1[1][i] = 0.f;
        g_c0[i] = 0.f;    g_c1[i] = 0.f;
    }
}

// ---------------------------------------------------------------------------
// Precompute: Gpre[t][b][j] = embed[y[b][t]] . Wih0[j] + bih0[j] + bhh0[j]
// tf32 mma, block tile 64(m) x 64(n), K = 512. grid = (4096/64, 256)
// ---------------------------------------------------------------------------
__global__ void __launch_bounds__(128) precompute_kernel(
    const int* __restrict__ y, const float* __restrict__ embed,
    const float* __restrict__ Wih0, const float* __restrict__ bih0,
    const float* __restrict__ bhh0)
{
    __shared__ unsigned As[64][36];
    __shared__ unsigned Bs[64][36];
    __shared__ int ysm[64];

    int tid  = threadIdx.x;
    int lane = tid & 31;
    int w    = tid >> 5;
    int n0   = blockIdx.x * 64;
    int m0   = blockIdx.y * 64;   // m = t*64 + b  => whole tile shares t
    int t    = blockIdx.y;

    if (tid < 64) ysm[tid] = y[tid * TT + t];   // b = tid
    __syncthreads();

    float acc[8][4];
#pragma unroll
    for (int i = 0; i < 8; i++)
#pragma unroll
        for (int j = 0; j < 4; j++) acc[i][j] = 0.f;

    for (int kc = 0; kc < HD; kc += 32) {
#pragma unroll
        for (int r = 0; r < 4; r++) {
            int e = tid + r * 128;
            int m = e >> 3, q = e & 7;
            float4 v = *(const float4*)(embed + (long long)ysm[m] * HD + kc + q * 4);
            uint4 uv = make_uint4(f2tf(v.x), f2tf(v.y), f2tf(v.z), f2tf(v.w));
            *(uint4*)&As[m][q * 4] = uv;
        }
#pragma unroll
        for (int r = 0; r < 4; r++) {
            int e = tid + r * 128;
            int m = e >> 3, q = e & 7;
            float4 v = *(const float4*)(Wih0 + (long long)(n0 + m) * HD + kc + q * 4);
            uint4 uv = make_uint4(f2tf(v.x), f2tf(v.y), f2tf(v.z), f2tf(v.w));
            *(uint4*)&Bs[m][q * 4] = uv;
        }
        __syncthreads();
#pragma unroll
        for (int kk = 0; kk < 32; kk += 8) {
            unsigned a[4][4], b[2][2];
#pragma unroll
            for (int mi = 0; mi < 4; mi++) {
                int row = mi * 16 + (lane >> 2);
                int col = kk + (lane & 3);
                a[mi][0] = As[row][col];
                a[mi][1] = As[row + 8][col];
                a[mi][2] = As[row][col + 4];
                a[mi][3] = As[row + 8][col + 4];
            }
#pragma unroll
            for (int nj = 0; nj < 2; nj++) {
                int br = w * 16 + nj * 8 + (lane >> 2);
                b[nj][0] = Bs[br][kk + (lane & 3)];
                b[nj][1] = Bs[br][kk + 4 + (lane & 3)];
            }
#pragma unroll
            for (int mi = 0; mi < 4; mi++)
#pragma unroll
                for (int nj = 0; nj < 2; nj++)
                    mma8(acc[mi * 2 + nj], a[mi], b[nj]);
        }
        __syncthreads();
    }

#pragma unroll
    for (int mi = 0; mi < 4; mi++) {
#pragma unroll
        for (int nj = 0; nj < 2; nj++) {
            float* c = acc[mi * 2 + nj];
            int row = m0 + mi * 16 + (lane >> 2);
            int col = n0 + w * 16 + nj * 8 + (lane & 3) * 2;
            float bb0 = bih0[col] + bhh0[col];
            float bb1 = bih0[col + 1] + bhh0[col + 1];
            *(float2*)(g_Gpre + (long long)row * NG + col) =
                make_float2(c[0] + bb0, c[1] + bb1);
            *(float2*)(g_Gpre + (long long)(row + 8) * NG + col) =
                make_float2(c[2] + bb0, c[3] + bb1);
        }
    }
}

// ---------------------------------------------------------------------------
// LSTM cell kernel. Block handles 8 hidden units x 4 gates (32 N-cols),
// full batch M=64, K=1024 per source (layer1 has two sources).
// 8 warps: warp = (m-half, gate). Fused activation epilogue.
// grid = 128 blocks, 256 threads.
// ---------------------------------------------------------------------------
__device__ __forceinline__ void cell_ld(const float* __restrict__ A,
                                        const float* __restrict__ W,
                                        int kc, int tid, int u0,
                                        float4* pa, float4* pb) {
#pragma unroll
    for (int r = 0; r < 2; r++) {
        int e = tid + r * 256;
        int m = e >> 3, q = e & 7;
        pa[r] = *(const float4*)(A + (long long)m * HU + kc + q * 4);
    }
    int m = tid >> 3, q = tid & 7;
    int wrow = (m >> 3) * HU + u0 + (m & 7);   // gate*1024 + unit
    *pb = *(const float4*)(W + (long long)wrow * HU + kc + q * 4);
}

__global__ void __launch_bounds__(256) cell_kernel(
    int layer, int pp,
    const float* __restrict__ W1, const float* __restrict__ W2,
    const float* __restrict__ bias1, const float* __restrict__ bias2,
    float* __restrict__ out_seq, int t)
{
    __shared__ unsigned sbuf[64 * 36 + 32 * 36];
    unsigned (*As)[36] = (unsigned(*)[36])sbuf;
    unsigned (*Bs)[36] = (unsigned(*)[36])(sbuf + 64 * 36);
    float* gsm = (float*)sbuf;                  // [4][64][8] after GEMM phase

    int tid  = threadIdx.x;
    int lane = tid & 31;
    int w    = tid >> 5;
    int mh   = w >> 2;       // m half: rows mh*32 .. +32
    int gt   = w & 3;        // gate index handled by this warp
    int u0   = blockIdx.x * 8;

    const float* A1; const float* A2;
    float* c_state; float* h_out; const float* base;
    if (layer == 0) {
        A1 = g_h0[pp]; A2 = nullptr;
        c_state = g_c0; h_out = g_h0[pp ^ 1];
        base = g_Gpre + (long long)t * BQ * NG;
    } else {
        A1 = g_h0[pp ^ 1]; A2 = g_h1[pp];
        c_state = g_c1; h_out = g_h1[pp ^ 1];
        base = nullptr;
    }
    int nchunks = ((layer == 0) ? 1 : 2) * (HU / 32);

    float acc[2][4];
#pragma unroll
    for (int i = 0; i < 2; i++)
#pragma unroll
        for (int j = 0; j < 4; j++) acc[i][j] = 0.f;

    float4 pa[2]; float4 pb;
    cell_ld(A1, W1, 0, tid, u0, pa, &pb);

    for (int cc = 0; cc < nchunks; cc++) {
        // stage current prefetch into smem (tf32-converted)
#pragma unroll
        for (int r = 0; r < 2; r++) {
            int e = tid + r * 256;
            int m = e >> 3, q = e & 7;
            uint4 uv = make_uint4(f2tf(pa[r].x), f2tf(pa[r].y),
                                  f2tf(pa[r].z), f2tf(pa[r].w));
            *(uint4*)&As[m][q * 4] = uv;
        }
        {
            int m = tid >> 3, q = tid & 7;
            uint4 uv = make_uint4(f2tf(pb.x), f2tf(pb.y), f2tf(pb.z), f2tf(pb.w));
            *(uint4*)&Bs[m][q * 4] = uv;
        }
        __syncthreads();

        // prefetch next chunk (overlaps with MMA below)
        if (cc + 1 < nchunks) {
            int nc = cc + 1;
            int s  = nc >> 5;
            int kc = (nc & 31) * 32;
            cell_ld(s ? A2 : A1, s ? W2 : W1, kc, tid, u0, pa, &pb);
        }

#pragma unroll
        for (int kk = 0; kk < 32; kk += 8) {
            unsigned a[2][4], b[2];
#pragma unroll
            for (int mi = 0; mi < 2; mi++) {
                int row = mh * 32 + mi * 16 + (lane >> 2);
                int col = kk + (lane & 3);
                a[mi][0] = As[row][col];
                a[mi][1] = As[row + 8][col];
                a[mi][2] = As[row][col + 4];
                a[mi][3] = As[row + 8][col + 4];
            }
            {
                int br = gt * 8 + (lane >> 2);
                b[0] = Bs[br][kk + (lane & 3)];
                b[1] = Bs[br][kk + 4 + (lane & 3)];
            }
            mma8(acc[0], a[0], b);
            mma8(acc[1], a[1], b);
        }
        __syncthreads();
    }

    // ---- epilogue: gather gates across warps, apply LSTM update ----
#pragma unroll
    for (int mi = 0; mi < 2; mi++) {
        float* c = acc[mi];
        int row = mh * 32 + mi * 16 + (lane >> 2);
        int cb  = (lane & 3) * 2;
        *(float2*)&gsm[(gt * 64 + row) * 8 + cb]     = make_float2(c[0], c[1]);
        *(float2*)&gsm[(gt * 64 + row + 8) * 8 + cb] = make_float2(c[2], c[3]);
    }
    __syncthreads();

#pragma unroll
    for (int r = 0; r < 2; r++) {
        int e  = tid + r * 256;       // 512 (b,u) pairs
        int b  = e >> 3, uu = e & 7;
        int u  = u0 + uu;
        float gi = gsm[(0 * 64 + b) * 8 + uu];
        float gf = gsm[(1 * 64 + b) * 8 + uu];
        float gg = gsm[(2 * 64 + b) * 8 + uu];
        float go = gsm[(3 * 64 + b) * 8 + uu];
        if (layer == 0) {
            const float* gp = base + (long long)b * NG;
            gi += gp[u];
            gf += gp[HU + u];
            gg += gp[2 * HU + u];
            go += gp[3 * HU + u];
        } else {
            gi += bias1[u]          + bias2[u];
            gf += bias1[HU + u]     + bias2[HU + u];
            gg += bias1[2 * HU + u] + bias2[2 * HU + u];
            go += bias1[3 * HU + u] + bias2[3 * HU + u];
        }
        float si = 1.f / (1.f + expf(-gi));
        float sf = 1.f / (1.f + expf(-gf));
        float so = 1.f / (1.f + expf(-go));
        float tg = tanhf(gg);
        int idx = b * HU + u;
        float cv = sf * c_state[idx] + si * tg;
        c_state[idx] = cv;
        float hv = so * tanhf(cv);
        h_out[idx] = hv;
        if (layer == 1) out_seq[((long long)b * TT + t) * HU + u] = hv;
    }
}

// ---------------------------------------------------------------------------
extern "C" void kernel_launch(void* const* d_in, const int* in_sizes, int n_in,
                              void* d_out, int out_size) {
    const int*   y     = (const int*)  d_in[0];
    const float* embed = (const float*)d_in[1];
    const float* Wih0  = (const float*)d_in[2];
    const float* Whh0  = (const float*)d_in[3];
    const float* bih0  = (const float*)d_in[4];
    const float* bhh0  = (const float*)d_in[5];
    const float* Wih1  = (const float*)d_in[6];
    const float* Whh1  = (const float*)d_in[7];
    const float* bih1  = (const float*)d_in[8];
    const float* bhh1  = (const float*)d_in[9];
    float* out = (float*)d_out;

    zero_kernel<<<(BQ * HU + 255) / 256, 256>>>();
    precompute_kernel<<<dim3(NG / 64, TT), 128>>>(y, embed, Wih0, bih0, bhh0);

    for (int t = 0; t < TT; t++) {
        int pp = t & 1;
        cell_kernel<<<HU / 8, 256>>>(0, pp, Whh0, nullptr, nullptr, nullptr,
                                     nullptr, t);
        cell_kernel<<<HU / 8, 256>>>(1, pp, Wih1, Whh1, bih1, bhh1, out, t);
    }
    (void)in_sizes; (void)n_in; (void)out_size;
}

// round 3
// speedup vs baseline: 1.9691x; 1.9691x over previous
#include <cuda_runtime.h>
#include <cuda_fp16.h>

#define BQ 64
#define TT 256
#define HU 1024
#define HD 512
#define NG 4096
#define NBLK 128
#define UPB 8           // hidden units per block
#define NKT 192         // k-tiles of 16: 64 (Whh0) + 64 (Wih1) + 64 (Whh1)

// ---------------- static device scratch (no allocation allowed) -------------
__device__ float  g_Gpre[(size_t)TT * BQ * NG];      // 256 MiB: Wih0-path + biases
__device__ __half g_h0[2][BQ * HU];
__device__ __half g_h1[2][BQ * HU];
__device__ uint2  g_Wf[(size_t)NBLK * 4 * NKT * 32]; // fp16 weights, mma-fragment order
__device__ unsigned g_flag;
__device__ unsigned g_count;

// smem layout for persistent kernel
#define WSM_BYTES   (4 * NKT * 32 * 8)               // 196608
#define ABUF_OFF    WSM_BYTES
#define ABUF_HALF   (64 * 72)                        // one buffer, halves
#define GSM_OFF     (ABUF_OFF + 2 * ABUF_HALF * 2)   // + 18432
#define CSM_OFF     (GSM_OFF + 4 * 64 * 8 * 4)       // + 8192
#define BSUM_OFF    (CSM_OFF + 2 * 512 * 4)          // + 4096
#define SMEM_TOTAL  (BSUM_OFF + 32 * 4)              // 227456

// ---------------- helpers ----------------------------------------------------
__device__ __forceinline__ unsigned f2tf(float f) {
    unsigned r;
    asm("cvt.rna.tf32.f32 %0, %1;" : "=r"(r) : "f"(f));
    return r;
}
__device__ __forceinline__ void mma8(float* c, const unsigned* a, const unsigned* b) {
    asm volatile(
        "mma.sync.aligned.m16n8k8.row.col.f32.tf32.tf32.f32 "
        "{%0,%1,%2,%3}, {%4,%5,%6,%7}, {%8,%9}, {%0,%1,%2,%3};\n"
        : "+f"(c[0]), "+f"(c[1]), "+f"(c[2]), "+f"(c[3])
        : "r"(a[0]), "r"(a[1]), "r"(a[2]), "r"(a[3]), "r"(b[0]), "r"(b[1]));
}
__device__ __forceinline__ void mma16h(float* c, const unsigned* a, const unsigned* b) {
    asm volatile(
        "mma.sync.aligned.m16n8k16.row.col.f32.f16.f16.f32 "
        "{%0,%1,%2,%3}, {%4,%5,%6,%7}, {%8,%9}, {%0,%1,%2,%3};\n"
        : "+f"(c[0]), "+f"(c[1]), "+f"(c[2]), "+f"(c[3])
        : "r"(a[0]), "r"(a[1]), "r"(a[2]), "r"(a[3]), "r"(b[0]), "r"(b[1]));
}
__device__ __forceinline__ void ldmA(unsigned* a, const __half* Abuf, int mrow,
                                     int kcol, int lane) {
    int r = lane & 7, sel = lane >> 3;
    int row = mrow + r + (sel & 1) * 8;
    int col = kcol + (sel >> 1) * 8;
    unsigned addr = (unsigned)__cvta_generic_to_shared(Abuf + row * 72 + col);
    asm volatile("ldmatrix.sync.aligned.m8n8.x4.shared.b16 {%0,%1,%2,%3}, [%4];"
                 : "=r"(a[0]), "=r"(a[1]), "=r"(a[2]), "=r"(a[3]) : "r"(addr));
}

// ---------------- init -------------------------------------------------------
__global__ void zero_kernel() {
    int i = blockIdx.x * blockDim.x + threadIdx.x;
    int n = BQ * HU / 2;
    if (i < n) {
        ((unsigned*)g_h0[0])[i] = 0u;
        ((unsigned*)g_h1[0])[i] = 0u;
    }
    if (i == 0) { g_flag = 0u; g_count = 0u; }
}

// ---------------- weight packing: fp32 -> fp16 B-fragment order --------------
// For block bk, gate gt, ktile kt, lane l:
//   n (weight row) = gt*HU + bk*8 + (l>>2)
//   k pairs: (2*(l&3), +1) and (+8, +9) within the ktile's 16-wide K window.
__global__ void __launch_bounds__(256) prep_weights(
    const float* __restrict__ Whh0, const float* __restrict__ Wih1,
    const float* __restrict__ Whh1)
{
    int bk = blockIdx.x;
    int u0 = bk * UPB;
    for (int idx = threadIdx.x; idx < 4 * NKT * 32; idx += 256) {
        int lane = idx & 31;
        int kt   = (idx >> 5) % NKT;
        int gt   = (idx >> 5) / NKT;
        const float* W; int kbase;
        if (kt < 64)       { W = Whh0; kbase = kt * 16; }
        else if (kt < 128) { W = Wih1; kbase = (kt - 64) * 16; }
        else               { W = Whh1; kbase = (kt - 128) * 16; }
        int row = gt * HU + u0 + (lane >> 2);
        const float* p = W + (size_t)row * HU + kbase + 2 * (lane & 3);
        __half2 lo = __floats2half2_rn(p[0], p[1]);
        __half2 hi = __floats2half2_rn(p[8], p[9]);
        uint2 v;
        v.x = *(unsigned*)&lo;
        v.y = *(unsigned*)&hi;
        g_Wf[(((size_t)bk * 4 + gt) * NKT + kt) * 32 + lane] = v;
    }
}

// ---------------- precompute: Gpre = embed[y] @ Wih0^T + bih0 + bhh0 ---------
__global__ void __launch_bounds__(128) precompute_kernel(
    const int* __restrict__ y, const float* __restrict__ embed,
    const float* __restrict__ Wih0, const float* __restrict__ bih0,
    const float* __restrict__ bhh0)
{
    __shared__ unsigned As[64][36];
    __shared__ unsigned Bs[64][36];
    __shared__ int ysm[64];

    int tid  = threadIdx.x;
    int lane = tid & 31;
    int w    = tid >> 5;
    int n0   = blockIdx.x * 64;
    int m0   = blockIdx.y * 64;
    int t    = blockIdx.y;

    if (tid < 64) ysm[tid] = y[tid * TT + t];
    __syncthreads();

    float acc[8][4];
#pragma unroll
    for (int i = 0; i < 8; i++)
#pragma unroll
        for (int j = 0; j < 4; j++) acc[i][j] = 0.f;

    for (int kc = 0; kc < HD; kc += 32) {
#pragma unroll
        for (int r = 0; r < 4; r++) {
            int e = tid + r * 128;
            int m = e >> 3, q = e & 7;
            float4 v = *(const float4*)(embed + (size_t)ysm[m] * HD + kc + q * 4);
            uint4 uv = make_uint4(f2tf(v.x), f2tf(v.y), f2tf(v.z), f2tf(v.w));
            *(uint4*)&As[m][q * 4] = uv;
        }
#pragma unroll
        for (int r = 0; r < 4; r++) {
            int e = tid + r * 128;
            int m = e >> 3, q = e & 7;
            float4 v = *(const float4*)(Wih0 + (size_t)(n0 + m) * HD + kc + q * 4);
            uint4 uv = make_uint4(f2tf(v.x), f2tf(v.y), f2tf(v.z), f2tf(v.w));
            *(uint4*)&Bs[m][q * 4] = uv;
        }
        __syncthreads();
#pragma unroll
        for (int kk = 0; kk < 32; kk += 8) {
            unsigned a[4][4], b[2][2];
#pragma unroll
            for (int mi = 0; mi < 4; mi++) {
                int row = mi * 16 + (lane >> 2);
                int col = kk + (lane & 3);
                a[mi][0] = As[row][col];
                a[mi][1] = As[row + 8][col];
                a[mi][2] = As[row][col + 4];
                a[mi][3] = As[row + 8][col + 4];
            }
#pragma unroll
            for (int nj = 0; nj < 2; nj++) {
                int br = w * 16 + nj * 8 + (lane >> 2);
                b[nj][0] = Bs[br][kk + (lane & 3)];
                b[nj][1] = Bs[br][kk + 4 + (lane & 3)];
            }
#pragma unroll
            for (int mi = 0; mi < 4; mi++)
#pragma unroll
                for (int nj = 0; nj < 2; nj++)
                    mma8(acc[mi * 2 + nj], a[mi], b[nj]);
        }
        __syncthreads();
    }

#pragma unroll
    for (int mi = 0; mi < 4; mi++) {
#pragma unroll
        for (int nj = 0; nj < 2; nj++) {
            float* c = acc[mi * 2 + nj];
            int row = m0 + mi * 16 + (lane >> 2);
            int col = n0 + w * 16 + nj * 8 + (lane & 3) * 2;
            float bb0 = bih0[col] + bhh0[col];
            float bb1 = bih0[col + 1] + bhh0[col + 1];
            *(float2*)(g_Gpre + (size_t)row * NG + col) =
                make_float2(c[0] + bb0, c[1] + bb1);
            *(float2*)(g_Gpre + (size_t)(row + 8) * NG + col) =
                make_float2(c[2] + bb0, c[3] + bb1);
        }
    }
}

// ---------------- grid-wide barrier ------------------------------------------
__device__ __forceinline__ void gridbar(unsigned phase) {
    __syncthreads();
    if (threadIdx.x == 0) {
        __threadfence();
        unsigned v = atomicAdd(&g_count, 1u);
        if (v == phase * NBLK - 1u) {
            asm volatile("st.global.release.gpu.u32 [%0], %1;"
                         :: "l"(&g_flag), "r"(phase) : "memory");
        } else {
            unsigned f;
            do {
                asm volatile("ld.global.acquire.gpu.u32 %0, [%1];"
                             : "=r"(f) : "l"(&g_flag) : "memory");
            } while (f < phase);
        }
    }
    __syncthreads();
}

// ---------------- persistent LSTM kernel -------------------------------------
__global__ void __launch_bounds__(256, 1) lstm_persistent(
    const float* __restrict__ bih1, const float* __restrict__ bhh1,
    float* __restrict__ out)
{
    extern __shared__ char smem[];
    uint2*  Wsm  = (uint2*)smem;
    __half* Ab   = (__half*)(smem + ABUF_OFF);
    float*  gsm  = (float*)(smem + GSM_OFF);
    float*  csm  = (float*)(smem + CSM_OFF);
    float*  bsum = (float*)(smem + BSUM_OFF);

    const int tid  = threadIdx.x;
    const int lane = tid & 31;
    const int w    = tid >> 5;
    const int mh   = w >> 2;      // batch half (rows mh*32 .. +32)
    const int gt   = w & 3;       // gate index
    const int bk   = blockIdx.x;
    const int u0   = bk * UPB;

    // load this block's fp16 weight slice into smem (stays for all 256 steps)
    {
        const uint4* src = (const uint4*)(g_Wf + (size_t)bk * 4 * NKT * 32);
        uint4* dst = (uint4*)Wsm;
        for (int i = tid; i < 4 * NKT * 32 / 2; i += 256) dst[i] = src[i];
    }
    if (tid < 32) {
        int g = tid >> 3, uu = tid & 7;
        bsum[tid] = bih1[g * HU + u0 + uu] + bhh1[g * HU + u0 + uu];
    }
    for (int i = tid; i < 1024; i += 256) csm[i] = 0.f;
    __syncthreads();

    const int e0 = tid, e1 = tid + 256;
    const int r0 = e0 >> 3, q0 = e0 & 7;
    const int r1 = e1 >> 3, q1 = e1 & 7;

    for (int t = 0; t < TT; ++t) {
        const int pp = t & 1;
        const __half* h0r = g_h0[pp];
        __half*       h0w = g_h0[pp ^ 1];
        const __half* h1r = g_h1[pp];
        __half*       h1w = g_h1[pp ^ 1];

#pragma unroll
        for (int layer = 0; layer < 2; ++layer) {
            const int nch    = layer ? 32 : 16;
            const int ktbase = layer ? 64 : 0;

            float acc[2][2][4];   // [mtile][kparity][4]
#pragma unroll
            for (int i = 0; i < 2; i++)
#pragma unroll
                for (int j = 0; j < 2; j++)
#pragma unroll
                    for (int k = 0; k < 4; k++) acc[i][j][k] = 0.f;

            // preload chunk 0
            {
                const __half* src = layer ? h0w : h0r;
                uint4 v0 = *(const uint4*)(src + (size_t)r0 * HU + q0 * 8);
                uint4 v1 = *(const uint4*)(src + (size_t)r1 * HU + q1 * 8);
                *(uint4*)(Ab + r0 * 72 + q0 * 8) = v0;
                *(uint4*)(Ab + r1 * 72 + q1 * 8) = v1;
            }
            __syncthreads();

            for (int c = 0; c < nch; ++c) {
                const __half* cur = Ab + (c & 1) * ABUF_HALF;
                uint4 v0, v1;
                bool more = (c + 1 < nch);
                if (more) {
                    int nc = c + 1;
                    const __half* src;
                    int koff;
                    if (layer == 0)      { src = h0r; koff = nc * 64; }
                    else if (nc < 16)    { src = h0w; koff = nc * 64; }
                    else                 { src = h1r; koff = (nc - 16) * 64; }
                    v0 = *(const uint4*)(src + (size_t)r0 * HU + koff + q0 * 8);
                    v1 = *(const uint4*)(src + (size_t)r1 * HU + koff + q1 * 8);
                }
#pragma unroll
                for (int kt2 = 0; kt2 < 4; ++kt2) {
                    unsigned b[2];
                    uint2 bb = Wsm[(gt * NKT + ktbase + c * 4 + kt2) * 32 + lane];
                    b[0] = bb.x; b[1] = bb.y;
                    unsigned a0[4], a1[4];
                    ldmA(a0, cur, mh * 32,      kt2 * 16, lane);
                    ldmA(a1, cur, mh * 32 + 16, kt2 * 16, lane);
                    mma16h(acc[0][kt2 & 1], a0, b);
                    mma16h(acc[1][kt2 & 1], a1, b);
                }
                if (more) {
                    __half* nxt = Ab + ((c + 1) & 1) * ABUF_HALF;
                    *(uint4*)(nxt + r0 * 72 + q0 * 8) = v0;
                    *(uint4*)(nxt + r1 * 72 + q1 * 8) = v1;
                }
                __syncthreads();
            }

            // fold k-parity accumulators, scatter to gsm
#pragma unroll
            for (int mt = 0; mt < 2; ++mt) {
                float c0 = acc[mt][0][0] + acc[mt][1][0];
                float c1 = acc[mt][0][1] + acc[mt][1][1];
                float c2 = acc[mt][0][2] + acc[mt][1][2];
                float c3 = acc[mt][0][3] + acc[mt][1][3];
                int row = mh * 32 + mt * 16 + (lane >> 2);
                int cb  = 2 * (lane & 3);
                *(float2*)&gsm[(gt * 64 + row) * 8 + cb]       = make_float2(c0, c1);
                *(float2*)&gsm[(gt * 64 + row + 8) * 8 + cb]   = make_float2(c2, c3);
            }
            __syncthreads();

            // LSTM epilogue: 512 (b,u) pairs
#pragma unroll
            for (int r = 0; r < 2; ++r) {
                int e  = tid + r * 256;
                int b  = e >> 3, uu = e & 7;
                int u  = u0 + uu;
                float gi = gsm[(0 * 64 + b) * 8 + uu];
                float gf = gsm[(1 * 64 + b) * 8 + uu];
                float gg = gsm[(2 * 64 + b) * 8 + uu];
                float go = gsm[(3 * 64 + b) * 8 + uu];
                if (layer == 0) {
                    const float* gp = g_Gpre + ((size_t)t * BQ + b) * NG;
                    gi += gp[u];
                    gf += gp[HU + u];
                    gg += gp[2 * HU + u];
                    go += gp[3 * HU + u];
                } else {
                    gi += bsum[uu];
                    gf += bsum[8 + uu];
                    gg += bsum[16 + uu];
                    go += bsum[24 + uu];
                }
                float si = 1.f / (1.f + expf(-gi));
                float sf = 1.f / (1.f + expf(-gf));
                float so = 1.f / (1.f + expf(-go));
                float tg = tanhf(gg);
                float* cc = csm + layer * 512 + b * 8 + uu;
                float cv = sf * (*cc) + si * tg;
                *cc = cv;
                float hv = so * tanhf(cv);
                if (layer == 0) {
                    h0w[b * HU + u] = __float2half_rn(hv);
                } else {
                    h1w[b * HU + u] = __float2half_rn(hv);
                    out[((size_t)b * TT + t) * HU + u] = hv;
                }
            }

            // grid-wide sync (skip after the very last epilogue)
            unsigned phase = 2u * t + 1u + (unsigned)layer;
            if (phase < 2u * TT) gridbar(phase);
        }
    }
}

// ---------------------------------------------------------------------------
extern "C" void kernel_launch(void* const* d_in, const int* in_sizes, int n_in,
                              void* d_out, int out_size) {
    const int*   y     = (const int*)  d_in[0];
    const float* embed = (const float*)d_in[1];
    const float* Wih0  = (const float*)d_in[2];
    const float* Whh0  = (const float*)d_in[3];
    const float* bih0  = (const float*)d_in[4];
    const float* bhh0  = (const float*)d_in[5];
    const float* Wih1  = (const float*)d_in[6];
    const float* Whh1  = (const float*)d_in[7];
    const float* bih1  = (const float*)d_in[8];
    const float* bhh1  = (const float*)d_in[9];
    float* out = (float*)d_out;

    cudaFuncSetAttribute(lstm_persistent,
                         cudaFuncAttributeMaxDynamicSharedMemorySize, SMEM_TOTAL);

    zero_kernel<<<(BQ * HU / 2 + 255) / 256, 256>>>();
    prep_weights<<<NBLK, 256>>>(Whh0, Wih1, Whh1);
    precompute_kernel<<<dim3(NG / 64, TT), 128>>>(y, embed, Wih0, bih0, bhh0);
    lstm_persistent<<<NBLK, 256, SMEM_TOTAL>>>(bih1, bhh1, out);

    (void)in_sizes; (void)n_in; (void)out_size;
}

// round 4
// speedup vs baseline: 2.4710x; 1.2548x over previous
#include <cuda_runtime.h>
#include <cuda_fp16.h>

#define BQ 64
#define TT 256
#define HU 1024
#define HD 512
#define NG 4096
#define NBLK 128
#define UPB 8           // hidden units per block
#define NKT 192         // k16 tiles: 64 (Whh0) + 64 (Wih1) + 64 (Whh1)

// ---------------- static device scratch (no allocation allowed) -------------
__device__ float  g_Gpre[(size_t)TT * BQ * NG];      // precomputed input gates (+biases)
__device__ __half g_h0[2][BQ * HU];
__device__ __half g_h1[2][BQ * HU];
__device__ uint2  g_Wf[(size_t)NBLK * 4 * NKT * 32]; // fp16 weights, mma-fragment order
__device__ unsigned g_flag;
__device__ unsigned g_count;

// smem layout for persistent kernel
#define WSM_BYTES   (4 * NKT * 32 * 8)               // 196608
#define ABUF_OFF    WSM_BYTES
#define STAGE_BYTES (64 * 72 * 2)                    // 9216 per stage
#define NSTAGE      3
#define CSM_OFF     (ABUF_OFF + NSTAGE * STAGE_BYTES)   // 224256
#define BSUM_OFF    (CSM_OFF + 2 * 512 * 4)             // 228352
#define SMEM_TOTAL  (BSUM_OFF + 32 * 4)                 // 228480

// ---------------- helpers ----------------------------------------------------
__device__ __forceinline__ unsigned f2tf(float f) {
    unsigned r;
    asm("cvt.rna.tf32.f32 %0, %1;" : "=r"(r) : "f"(f));
    return r;
}
__device__ __forceinline__ void mma8(float* c, const unsigned* a, const unsigned* b) {
    asm volatile(
        "mma.sync.aligned.m16n8k8.row.col.f32.tf32.tf32.f32 "
        "{%0,%1,%2,%3}, {%4,%5,%6,%7}, {%8,%9}, {%0,%1,%2,%3};\n"
        : "+f"(c[0]), "+f"(c[1]), "+f"(c[2]), "+f"(c[3])
        : "r"(a[0]), "r"(a[1]), "r"(a[2]), "r"(a[3]), "r"(b[0]), "r"(b[1]));
}
__device__ __forceinline__ void mma16h(float* c, const unsigned* a, const unsigned* b) {
    asm volatile(
        "mma.sync.aligned.m16n8k16.row.col.f32.f16.f16.f32 "
        "{%0,%1,%2,%3}, {%4,%5,%6,%7}, {%8,%9}, {%0,%1,%2,%3};\n"
        : "+f"(c[0]), "+f"(c[1]), "+f"(c[2]), "+f"(c[3])
        : "r"(a[0]), "r"(a[1]), "r"(a[2]), "r"(a[3]), "r"(b[0]), "r"(b[1]));
}
__device__ __forceinline__ void ldmA(unsigned* a, const __half* Abuf, int mrow,
                                     int kcol, int lane) {
    int row = mrow + (lane & 7) + ((lane >> 3) & 1) * 8;
    int col = kcol + (lane >> 4) * 8;
    unsigned addr = (unsigned)__cvta_generic_to_shared(Abuf + row * 72 + col);
    asm volatile("ldmatrix.sync.aligned.m8n8.x4.shared.b16 {%0,%1,%2,%3}, [%4];"
                 : "=r"(a[0]), "=r"(a[1]), "=r"(a[2]), "=r"(a[3]) : "r"(addr));
}

// ---------------- init -------------------------------------------------------
__global__ void zero_kernel() {
    int i = blockIdx.x * blockDim.x + threadIdx.x;
    int n = BQ * HU / 2;
    if (i < n) {
        ((unsigned*)g_h0[0])[i] = 0u;
        ((unsigned*)g_h1[0])[i] = 0u;
    }
    if (i == 0) { g_flag = 0u; g_count = 0u; }
}

// ---------------- weight packing: fp32 -> fp16 B-fragment order --------------
__global__ void __launch_bounds__(256) prep_weights(
    const float* __restrict__ Whh0, const float* __restrict__ Wih1,
    const float* __restrict__ Whh1)
{
    int bk = blockIdx.x;
    int u0 = bk * UPB;
    for (int idx = threadIdx.x; idx < 4 * NKT * 32; idx += 256) {
        int lane = idx & 31;
        int kt   = (idx >> 5) % NKT;
        int gt   = (idx >> 5) / NKT;
        const float* W; int kbase;
        if (kt < 64)       { W = Whh0; kbase = kt * 16; }
        else if (kt < 128) { W = Wih1; kbase = (kt - 64) * 16; }
        else               { W = Whh1; kbase = (kt - 128) * 16; }
        int row = gt * HU + u0 + (lane >> 2);
        const float* p = W + (size_t)row * HU + kbase + 2 * (lane & 3);
        __half2 lo = __floats2half2_rn(p[0], p[1]);
        __half2 hi = __floats2half2_rn(p[8], p[9]);
        uint2 v;
        v.x = *(unsigned*)&lo;
        v.y = *(unsigned*)&hi;
        g_Wf[(((size_t)bk * 4 + gt) * NKT + kt) * 32 + lane] = v;
    }
}

// ---------------- precompute: Gpre = embed[y] @ Wih0^T + bih0 + bhh0 ---------
__global__ void __launch_bounds__(128) precompute_kernel(
    const int* __restrict__ y, const float* __restrict__ embed,
    const float* __restrict__ Wih0, const float* __restrict__ bih0,
    const float* __restrict__ bhh0)
{
    __shared__ unsigned As[64][36];
    __shared__ unsigned Bs[64][36];
    __shared__ int ysm[64];

    int tid  = threadIdx.x;
    int lane = tid & 31;
    int w    = tid >> 5;
    int n0   = blockIdx.x * 64;
    int m0   = blockIdx.y * 64;
    int t    = blockIdx.y;

    if (tid < 64) ysm[tid] = y[tid * TT + t];
    __syncthreads();

    float acc[8][4];
#pragma unroll
    for (int i = 0; i < 8; i++)
#pragma unroll
        for (int j = 0; j < 4; j++) acc[i][j] = 0.f;

    for (int kc = 0; kc < HD; kc += 32) {
#pragma unroll
        for (int r = 0; r < 4; r++) {
            int e = tid + r * 128;
            int m = e >> 3, q = e & 7;
            float4 v = *(const float4*)(embed + (size_t)ysm[m] * HD + kc + q * 4);
            uint4 uv = make_uint4(f2tf(v.x), f2tf(v.y), f2tf(v.z), f2tf(v.w));
            *(uint4*)&As[m][q * 4] = uv;
        }
#pragma unroll
        for (int r = 0; r < 4; r++) {
            int e = tid + r * 128;
            int m = e >> 3, q = e & 7;
            float4 v = *(const float4*)(Wih0 + (size_t)(n0 + m) * HD + kc + q * 4);
            uint4 uv = make_uint4(f2tf(v.x), f2tf(v.y), f2tf(v.z), f2tf(v.w));
            *(uint4*)&Bs[m][q * 4] = uv;
        }
        __syncthreads();
#pragma unroll
        for (int kk = 0; kk < 32; kk += 8) {
            unsigned a[4][4], b[2][2];
#pragma unroll
            for (int mi = 0; mi < 4; mi++) {
                int row = mi * 16 + (lane >> 2);
                int col = kk + (lane & 3);
                a[mi][0] = As[row][col];
                a[mi][1] = As[row + 8][col];
                a[mi][2] = As[row][col + 4];
                a[mi][3] = As[row + 8][col + 4];
            }
#pragma unroll
            for (int nj = 0; nj < 2; nj++) {
                int br = w * 16 + nj * 8 + (lane >> 2);
                b[nj][0] = Bs[br][kk + (lane & 3)];
                b[nj][1] = Bs[br][kk + 4 + (lane & 3)];
            }
#pragma unroll
            for (int mi = 0; mi < 4; mi++)
#pragma unroll
                for (int nj = 0; nj < 2; nj++)
                    mma8(acc[mi * 2 + nj], a[mi], b[nj]);
        }
        __syncthreads();
    }

#pragma unroll
    for (int mi = 0; mi < 4; mi++) {
#pragma unroll
        for (int nj = 0; nj < 2; nj++) {
            float* c = acc[mi * 2 + nj];
            int row = m0 + mi * 16 + (lane >> 2);
            int col = n0 + w * 16 + nj * 8 + (lane & 3) * 2;
            float bb0 = bih0[col] + bhh0[col];
            float bb1 = bih0[col + 1] + bhh0[col + 1];
            *(float2*)(g_Gpre + (size_t)row * NG + col) =
                make_float2(c[0] + bb0, c[1] + bb1);
            *(float2*)(g_Gpre + (size_t)(row + 8) * NG + col) =
                make_float2(c[2] + bb0, c[3] + bb1);
        }
    }
}

// ---------------- grid-wide barrier ------------------------------------------
__device__ __forceinline__ void gridbar(unsigned phase) {
    __syncthreads();
    if (threadIdx.x == 0) {
        __threadfence();
        unsigned v = atomicAdd(&g_count, 1u);
        if (v == phase * NBLK - 1u) {
            asm volatile("st.global.release.gpu.u32 [%0], %1;"
                         :: "l"(&g_flag), "r"(phase) : "memory");
        } else {
            unsigned f;
            do {
                asm volatile("ld.global.acquire.gpu.u32 %0, [%1];"
                             : "=r"(f) : "l"(&g_flag) : "memory");
            } while (f < phase);
        }
    }
    __syncthreads();
}

// ---------------- persistent LSTM kernel -------------------------------------
__global__ void __launch_bounds__(256, 1) lstm_persistent(
    const float* __restrict__ bih1, const float* __restrict__ bhh1,
    float* __restrict__ out)
{
    extern __shared__ char smem[];
    uint2* Wsm  = (uint2*)smem;
    char*  AbC  = smem + ABUF_OFF;
    float* gsm  = (float*)(smem + ABUF_OFF);     // alias (used only post-GEMM)
    float* csm  = (float*)(smem + CSM_OFF);
    float* bsum = (float*)(smem + BSUM_OFF);

    const int tid  = threadIdx.x;
    const int lane = tid & 31;
    const int w    = tid >> 5;
    const int mh   = w & 1;       // batch half (rows mh*32 .. +32)
    const int kq   = w >> 1;      // k16 quarter within 64-wide chunk
    const int bk   = blockIdx.x;
    const int u0   = bk * UPB;

    const unsigned ab_base = (unsigned)__cvta_generic_to_shared(AbC);

    // load block's fp16 weight slice into smem (resident for all 256 steps)
    {
        const uint4* src = (const uint4*)(g_Wf + (size_t)bk * 4 * NKT * 32);
        uint4* dst = (uint4*)Wsm;
        for (int i = tid; i < 4 * NKT * 32 / 2; i += 256) dst[i] = src[i];
    }
    if (tid < 32) {
        int g = tid >> 3, uu = tid & 7;
        bsum[tid] = bih1[g * HU + u0 + uu] + bhh1[g * HU + u0 + uu];
    }
    for (int i = tid; i < 1024; i += 256) csm[i] = 0.f;
    __syncthreads();

    // epilogue (b,u) decomposition for the 2 passes
    const int b0 = tid >> 3, b1 = (tid + 256) >> 3;
    const int uu = tid & 7;
    const int u  = u0 + uu;

    for (int t = 0; t < TT; ++t) {
        const int pp = t & 1;
        const __half* h0r = g_h0[pp];
        __half*       h0w = g_h0[pp ^ 1];
        const __half* h1r = g_h1[pp];
        __half*       h1w = g_h1[pp ^ 1];

        // prefetch Gpre operands for this step's layer-0 epilogue
        float pre0[4], pre1[4];
        {
            const float* gp = g_Gpre + (size_t)t * BQ * NG;
#pragma unroll
            for (int g = 0; g < 4; g++) {
                pre0[g] = gp[(size_t)b0 * NG + g * HU + u];
                pre1[g] = gp[(size_t)b1 * NG + g * HU + u];
            }
        }

#pragma unroll
        for (int layer = 0; layer < 2; ++layer) {
            const int nch    = layer ? 32 : 16;
            const int ktbase = layer ? 64 : 0;

            float acc[2][4][4];
#pragma unroll
            for (int i = 0; i < 2; i++)
#pragma unroll
                for (int j = 0; j < 4; j++)
#pragma unroll
                    for (int k = 0; k < 4; k++) acc[i][j][k] = 0.f;

            // --- chunk issuer: 64 rows x 64 halves, 2x 16B cp.async/thread ---
            auto issue_chunk = [&](int c) {
                const __half* src; int koff;
                if (layer == 0)  { src = h0r; koff = c * 64; }
                else if (c < 16) { src = h0w; koff = c * 64; }
                else             { src = h1r; koff = (c - 16) * 64; }
                unsigned sbase = ab_base + (c % NSTAGE) * STAGE_BYTES;
#pragma unroll
                for (int j = 0; j < 2; j++) {
                    int e = tid + j * 256;
                    int r = e >> 3, sg = e & 7;
                    const __half* g = src + (size_t)r * HU + koff + sg * 8;
                    unsigned sa = sbase + (unsigned)(r * 72 + sg * 8) * 2u;
                    asm volatile("cp.async.cg.shared.global [%0], [%1], 16;"
                                 :: "r"(sa), "l"(g));
                }
            };

            issue_chunk(0);
            asm volatile("cp.async.commit_group;");
            issue_chunk(1);
            asm volatile("cp.async.commit_group;");

            for (int c = 0; c < nch; ++c) {
                asm volatile("cp.async.wait_group 1;");
                __syncthreads();
                if (c + 2 < nch) issue_chunk(c + 2);
                asm volatile("cp.async.commit_group;");

                const __half* cur = (const __half*)(AbC + (c % NSTAGE) * STAGE_BYTES);
                const int kti = ktbase + c * 4 + kq;
                unsigned a0[4], a1[4];
                ldmA(a0, cur, mh * 32,      kq * 16, lane);
                ldmA(a1, cur, mh * 32 + 16, kq * 16, lane);
#pragma unroll
                for (int gt = 0; gt < 4; gt++) {
                    uint2 bb = Wsm[(gt * NKT + kti) * 32 + lane];
                    mma16h(acc[0][gt], a0, (const unsigned*)&bb);
                    mma16h(acc[1][gt], a1, (const unsigned*)&bb);
                }
            }

            __syncthreads();   // all compute done before gsm aliases stage bufs

            // --- fold k-quarters: pass1 write (kq 0,1), pass2 RMW (kq 2,3) ---
            const int p   = kq & 1;
            const int row = mh * 32 + (lane >> 2);
            const int cb  = 2 * (lane & 3);
            if (kq < 2) {
#pragma unroll
                for (int mt = 0; mt < 2; mt++) {
#pragma unroll
                    for (int gt = 0; gt < 4; gt++) {
                        float* base = &gsm[(p * 4 + gt) * 512 + (row + mt * 16) * 8 + cb];
                        *(float2*)base        = make_float2(acc[mt][gt][0], acc[mt][gt][1]);
                        *(float2*)(base + 64) = make_float2(acc[mt][gt][2], acc[mt][gt][3]);
                    }
                }
            }
            __syncthreads();
            if (kq >= 2) {
#pragma unroll
                for (int mt = 0; mt < 2; mt++) {
#pragma unroll
                    for (int gt = 0; gt < 4; gt++) {
                        float* base = &gsm[(p * 4 + gt) * 512 + (row + mt * 16) * 8 + cb];
                        float2 v0 = *(float2*)base;
                        float2 v1 = *(float2*)(base + 64);
                        v0.x += acc[mt][gt][0]; v0.y += acc[mt][gt][1];
                        v1.x += acc[mt][gt][2]; v1.y += acc[mt][gt][3];
                        *(float2*)base        = v0;
                        *(float2*)(base + 64) = v1;
                    }
                }
            }
            __syncthreads();

            // --- LSTM epilogue: 512 (b,u) pairs across 256 threads ----------
#pragma unroll
            for (int r = 0; r < 2; ++r) {
                const int b = r ? b1 : b0;
                float gi = gsm[(0 * 4 + 0) * 512 + b * 8 + uu] + gsm[(1 * 4 + 0) * 512 + b * 8 + uu];
                float gf = gsm[(0 * 4 + 1) * 512 + b * 8 + uu] + gsm[(1 * 4 + 1) * 512 + b * 8 + uu];
                float gg = gsm[(0 * 4 + 2) * 512 + b * 8 + uu] + gsm[(1 * 4 + 2) * 512 + b * 8 + uu];
                float go = gsm[(0 * 4 + 3) * 512 + b * 8 + uu] + gsm[(1 * 4 + 3) * 512 + b * 8 + uu];
                if (layer == 0) {
                    const float* pre = r ? pre1 : pre0;
                    gi += pre[0]; gf += pre[1]; gg += pre[2]; go += pre[3];
                } else {
                    gi += bsum[uu];      gf += bsum[8 + uu];
                    gg += bsum[16 + uu]; go += bsum[24 + uu];
                }
                float si = 1.f / (1.f + expf(-gi));
                float sf = 1.f / (1.f + expf(-gf));
                float so = 1.f / (1.f + expf(-go));
                float tg = tanhf(gg);
                float* cc = csm + layer * 512 + b * 8 + uu;
                float cv = sf * (*cc) + si * tg;
                *cc = cv;
                float hv = so * tanhf(cv);
                if (layer == 0) {
                    h0w[b * HU + u] = __float2half_rn(hv);
                } else {
                    h1w[b * HU + u] = __float2half_rn(hv);
                    out[((size_t)b * TT + t) * HU + u] = hv;
                }
            }

            unsigned phase = 2u * t + 1u + (unsigned)layer;
            if (phase < 2u * TT) gridbar(phase);
        }
    }
}

// ---------------------------------------------------------------------------
extern "C" void kernel_launch(void* const* d_in, const int* in_sizes, int n_in,
                              void* d_out, int out_size) {
    const int*   y     = (const int*)  d_in[0];
    const float* embed = (const float*)d_in[1];
    const float* Wih0  = (const float*)d_in[2];
    const float* Whh0  = (const float*)d_in[3];
    const float* bih0  = (const float*)d_in[4];
    const float* bhh0  = (const float*)d_in[5];
    const float* Wih1  = (const float*)d_in[6];
    const float* Whh1  = (const float*)d_in[7];
    const float* bih1  = (const float*)d_in[8];
    const float* bhh1  = (const float*)d_in[9];
    float* out = (float*)d_out;

    cudaFuncSetAttribute(lstm_persistent,
                         cudaFuncAttributeMaxDynamicSharedMemorySize, SMEM_TOTAL);

    zero_kernel<<<(BQ * HU / 2 + 255) / 256, 256>>>();
    prep_weights<<<NBLK, 256>>>(Whh0, Wih1, Whh1);
    precompute_kernel<<<dim3(NG / 64, TT), 128>>>(y, embed, Wih0, bih0, bhh0);
    lstm_persistent<<<NBLK, 256, SMEM_TOTAL>>>(bih1, bhh1, out);

    (void)in_sizes; (void)n_in; (void)out_size;
}

// round 5
// speedup vs baseline: 4.4213x; 1.7893x over previous
#include <cuda_runtime.h>
#include <cuda_fp16.h>

#define BQ 64
#define TT 256
#define HU 1024
#define HD 512
#define NG 4096
#define NBLK 128
#define UPB 8           // hidden units per block
#define NKT 192         // k16 tiles: 64 (Whh0) + 64 (Wih1) + 64 (Whh1)

// ---------------- static device scratch (no allocation allowed) -------------
__device__ float  g_Gpre[(size_t)TT * BQ * NG];
__device__ __half g_h0[2][BQ * HU];
__device__ __half g_h1[2][BQ * HU];
__device__ uint2  g_Wf[(size_t)NBLK * 4 * NKT * 32];   // recurrent weights, frag order
__device__ __half g_embed_h[(size_t)10000 * HD];       // fp16 embed
__device__ uint2  g_W0f[(size_t)(NG / 8) * 32 * 32];   // Wih0 fp16, frag order
__device__ unsigned g_cntA, g_cntB, g_flagA, g_flagB;

// smem layout for persistent kernel
#define WSM_BYTES   (4 * NKT * 32 * 8)                 // 196608
#define ABUF_OFF    WSM_BYTES
#define STAGE_BYTES 8192                               // 64 rows x 128B, SW128 swizzle
#define NSTAGE      4
#define BSUM_OFF    (ABUF_OFF + NSTAGE * STAGE_BYTES)  // 229376
#define SMEM_TOTAL  (BSUM_OFF + 128)                   // 229504

// ---------------- helpers ----------------------------------------------------
__device__ __forceinline__ void mma16h(float* c, const unsigned* a, const unsigned* b) {
    asm volatile(
        "mma.sync.aligned.m16n8k16.row.col.f32.f16.f16.f32 "
        "{%0,%1,%2,%3}, {%4,%5,%6,%7}, {%8,%9}, {%0,%1,%2,%3};\n"
        : "+f"(c[0]), "+f"(c[1]), "+f"(c[2]), "+f"(c[3])
        : "r"(a[0]), "r"(a[1]), "r"(a[2]), "r"(a[3]), "r"(b[0]), "r"(b[1]));
}
// A-frag load from pitch-72-halves smem tile (precompute kernel)
__device__ __forceinline__ void ldmA72(unsigned* a, const __half* buf, int mrow,
                                       int kcol, int lane) {
    int row = mrow + (lane & 7) + ((lane >> 3) & 1) * 8;
    int col = kcol + (lane >> 4) * 8;
    unsigned addr = (unsigned)__cvta_generic_to_shared(buf + row * 72 + col);
    asm volatile("ldmatrix.sync.aligned.m8n8.x4.shared.b16 {%0,%1,%2,%3}, [%4];"
                 : "=r"(a[0]), "=r"(a[1]), "=r"(a[2]), "=r"(a[3]) : "r"(addr));
}
// A-frag load from SW128-swizzled pitch-64-halves tile (persistent kernel)
__device__ __forceinline__ void ldmA_sw(unsigned* a, unsigned base, int mrow,
                                        int kcol, int lane) {
    int row = mrow + (lane & 7) + ((lane >> 3) & 1) * 8;
    unsigned sl = (unsigned)(kcol >> 3) + (unsigned)(lane >> 4);
    unsigned off = (unsigned)row * 128u + ((sl << 4) ^ (((unsigned)row & 7u) << 4));
    unsigned addr = base + off;
    asm volatile("ldmatrix.sync.aligned.m8n8.x4.shared.b16 {%0,%1,%2,%3}, [%4];"
                 : "=r"(a[0]), "=r"(a[1]), "=r"(a[2]), "=r"(a[3]) : "r"(addr));
}
__device__ __forceinline__ float fsig(float x) {
    return __fdividef(1.f, 1.f + __expf(-x));
}
__device__ __forceinline__ float ftanh(float x) {
    return __fdividef(2.f, 1.f + __expf(-2.f * x)) - 1.f;
}

// ---------------- init -------------------------------------------------------
__global__ void zero_kernel() {
    int i = blockIdx.x * blockDim.x + threadIdx.x;
    int n = BQ * HU / 2;
    if (i < n) {
        ((unsigned*)g_h0[0])[i] = 0u;
        ((unsigned*)g_h1[0])[i] = 0u;
    }
    if (i == 0) { g_cntA = 0u; g_cntB = 0u; g_flagA = 0u; g_flagB = 0u; }
}

// ---------------- fp32 -> fp16 embed conversion ------------------------------
__global__ void __launch_bounds__(256) conv_embed(const float* __restrict__ embed) {
    int i = blockIdx.x * blockDim.x + threadIdx.x;
    if (i < 10000 * HD / 4) {
        float4 v = ((const float4*)embed)[i];
        __half2 a = __floats2half2_rn(v.x, v.y);
        __half2 b = __floats2half2_rn(v.z, v.w);
        uint2 o;
        o.x = *(unsigned*)&a;
        o.y = *(unsigned*)&b;
        ((uint2*)g_embed_h)[i] = o;
    }
}

// ---------------- Wih0 fp16 fragment packing ---------------------------------
// g_W0f[(n8*32 + kt)*32 + lane]: n = n8*8 + (lane>>2), k = kt*16 + 2*(lane&3) (+{0,1},+{8,9})
__global__ void __launch_bounds__(256) pack_w0(const float* __restrict__ Wih0) {
    int idx = blockIdx.x * blockDim.x + threadIdx.x;
    if (idx < (NG / 8) * 32 * 32) {
        int lane = idx & 31;
        int kt   = (idx >> 5) & 31;
        int n8   = idx >> 10;
        int n = n8 * 8 + (lane >> 2);
        int k = kt * 16 + 2 * (lane & 3);
        const float* p = Wih0 + (size_t)n * HD + k;
        __half2 lo = __floats2half2_rn(p[0], p[1]);
        __half2 hi = __floats2half2_rn(p[8], p[9]);
        uint2 v;
        v.x = *(unsigned*)&lo;
        v.y = *(unsigned*)&hi;
        g_W0f[idx] = v;
    }
}

// ---------------- recurrent weight packing (as round 4) ----------------------
__global__ void __launch_bounds__(256) prep_weights(
    const float* __restrict__ Whh0, const float* __restrict__ Wih1,
    const float* __restrict__ Whh1)
{
    int bk = blockIdx.x;
    int u0 = bk * UPB;
    for (int idx = threadIdx.x; idx < 4 * NKT * 32; idx += 256) {
        int lane = idx & 31;
        int kt   = (idx >> 5) % NKT;
        int gt   = (idx >> 5) / NKT;
        const float* W; int kbase;
        if (kt < 64)       { W = Whh0; kbase = kt * 16; }
        else if (kt < 128) { W = Wih1; kbase = (kt - 64) * 16; }
        else               { W = Whh1; kbase = (kt - 128) * 16; }
        int row = gt * HU + u0 + (lane >> 2);
        const float* p = W + (size_t)row * HU + kbase + 2 * (lane & 3);
        __half2 lo = __floats2half2_rn(p[0], p[1]);
        __half2 hi = __floats2half2_rn(p[8], p[9]);
        uint2 v;
        v.x = *(unsigned*)&lo;
        v.y = *(unsigned*)&hi;
        g_Wf[(((size_t)bk * 4 + gt) * NKT + kt) * 32 + lane] = v;
    }
}

// ---------------- precompute: Gpre = embed[y] @ Wih0^T + bih0 + bhh0 ---------
// fp16 operands, fp32 accum. Tile: 128 m (2 t x 64 b) x 128 n. grid (32, 128).
__global__ void __launch_bounds__(256) precompute_kernel(
    const int* __restrict__ y, const float* __restrict__ bih0,
    const float* __restrict__ bhh0)
{
    __shared__ __half Asm[128 * 72];
    __shared__ uint2  Bsm[16 * 4 * 32];
    __shared__ int ysm[128];

    int tid  = threadIdx.x;
    int lane = tid & 31;
    int w    = tid >> 5;
    int wm   = w & 3;            // m quarter (32 rows)
    int wn   = w >> 2;           // n half (64 cols)
    int n0   = blockIdx.x * 128;
    int m0   = blockIdx.y * 128;

    if (tid < 128) ysm[tid] = y[(tid & 63) * TT + blockIdx.y * 2 + (tid >> 6)];
    __syncthreads();

    unsigned asm_base = (unsigned)__cvta_generic_to_shared(Asm);
    unsigned bsm_base = (unsigned)__cvta_generic_to_shared(Bsm);

    float acc[2][8][4];
#pragma unroll
    for (int i = 0; i < 2; i++)
#pragma unroll
        for (int j = 0; j < 8; j++)
#pragma unroll
            for (int k = 0; k < 4; k++) acc[i][j][k] = 0.f;

    for (int kc = 0; kc < 8; kc++) {   // 8 chunks of 64 K
        // stage A: 128 rows x 64 halves (pitch 72)
#pragma unroll
        for (int j = 0; j < 4; j++) {
            int e = tid + j * 256;
            int r = e >> 3, sg = e & 7;
            const __half* g = g_embed_h + (size_t)ysm[r] * HD + kc * 64 + sg * 8;
            unsigned dst = asm_base + (unsigned)(r * 72 + sg * 8) * 2u;
            asm volatile("cp.async.cg.shared.global [%0], [%1], 16;" :: "r"(dst), "l"(g));
        }
        // stage B: 16 n8-tiles x 4 kt x 32 lanes of uint2 (16KB)
#pragma unroll
        for (int j = 0; j < 4; j++) {
            int e = tid + j * 256;      // 16B unit index
            int n8l = e >> 6, w16 = e & 63;
            const uint2* src = g_W0f +
                ((size_t)(n0 / 8 + n8l) * 32 + kc * 4) * 32 + w16 * 2;
            unsigned dst = bsm_base + (unsigned)e * 16u;
            asm volatile("cp.async.cg.shared.global [%0], [%1], 16;" :: "r"(dst), "l"(src));
        }
        asm volatile("cp.async.commit_group;");
        asm volatile("cp.async.wait_group 0;");
        __syncthreads();

#pragma unroll
        for (int kt = 0; kt < 4; kt++) {
            unsigned a0[4], a1[4];
            ldmA72(a0, Asm, wm * 32,      kt * 16, lane);
            ldmA72(a1, Asm, wm * 32 + 16, kt * 16, lane);
#pragma unroll
            for (int nj = 0; nj < 8; nj++) {
                uint2 bb = Bsm[((wn * 8 + nj) * 4 + kt) * 32 + lane];
                mma16h(acc[0][nj], a0, (const unsigned*)&bb);
                mma16h(acc[1][nj], a1, (const unsigned*)&bb);
            }
        }
        __syncthreads();
    }

#pragma unroll
    for (int mt = 0; mt < 2; mt++) {
#pragma unroll
        for (int nj = 0; nj < 8; nj++) {
            float* c = acc[mt][nj];
            int row = wm * 32 + mt * 16 + (lane >> 2);
            int col = n0 + wn * 64 + nj * 8 + 2 * (lane & 3);
            float bb0 = bih0[col] + bhh0[col];
            float bb1 = bih0[col + 1] + bhh0[col + 1];
            *(float2*)(g_Gpre + (size_t)(m0 + row) * NG + col) =
                make_float2(c[0] + bb0, c[1] + bb1);
            *(float2*)(g_Gpre + (size_t)(m0 + row + 8) * NG + col) =
                make_float2(c[2] + bb0, c[3] + bb1);
        }
    }
}

// ---------------- persistent LSTM kernel -------------------------------------
__global__ void __launch_bounds__(256, 1) lstm_persistent(
    const float* __restrict__ bih1, const float* __restrict__ bhh1,
    float* __restrict__ out)
{
    extern __shared__ char smem[];
    uint2* Wsm  = (uint2*)smem;
    char*  AbC  = smem + ABUF_OFF;
    float* gsm  = (float*)(smem + ABUF_OFF);     // alias; used only post-GEMM
    float* bsum = (float*)(smem + BSUM_OFF);

    const int tid  = threadIdx.x;
    const int lane = tid & 31;
    const int w    = tid >> 5;
    const int mh   = w & 1;       // batch half
    const int kq   = w >> 1;      // k16 quarter within 64-wide chunk
    const int bk   = blockIdx.x;
    const int u0   = bk * UPB;

    const unsigned ab_base = (unsigned)__cvta_generic_to_shared(AbC);

    // resident weights
    {
        const uint4* src = (const uint4*)(g_Wf + (size_t)bk * 4 * NKT * 32);
        uint4* dst = (uint4*)Wsm;
        for (int i = tid; i < 4 * NKT * 32 / 2; i += 256) dst[i] = src[i];
    }
    if (tid < 32) {
        int g = tid >> 3, uu2 = tid & 7;
        bsum[tid] = bih1[g * HU + u0 + uu2] + bhh1[g * HU + u0 + uu2];
    }
    __syncthreads();

    const int b0 = tid >> 3, b1 = (tid + 256) >> 3;
    const int uu = tid & 7;
    const int u  = u0 + uu;

    float cr[2][2] = {{0.f, 0.f}, {0.f, 0.f}};   // c-state [layer][pair]
    float acc[2][4][4];

    const __half* h0r; __half* h0w; const __half* h1r; __half* h1w;

    auto issue_chunk = [&](int layer, int c) {
        const __half* src; int koff;
        if (layer == 0)  { src = h0r; koff = c * 64; }
        else if (c < 16) { src = h0w; koff = c * 64; }
        else             { src = h1r; koff = (c - 16) * 64; }
        unsigned sbase = ab_base + (unsigned)(c & 3) * STAGE_BYTES;
#pragma unroll
        for (int j = 0; j < 2; j++) {
            int e = tid + j * 256;
            int r = e >> 3, sg = e & 7;
            const __half* g = src + (size_t)r * HU + koff + sg * 8;
            unsigned dst = sbase + (unsigned)r * 128u +
                           (((unsigned)sg << 4) ^ (((unsigned)r & 7u) << 4));
            asm volatile("cp.async.cg.shared.global [%0], [%1], 16;" :: "r"(dst), "l"(g));
        }
        asm volatile("cp.async.commit_group;");
    };

    auto gemm_range = [&](int layer, int cb, int ce) {
        const int ktbase = layer ? 64 : 0;
        issue_chunk(layer, cb);
        if (cb + 1 < ce) issue_chunk(layer, cb + 1);
        if (cb + 2 < ce) issue_chunk(layer, cb + 2);
        for (int c = cb; c < ce; c++) {
            if (c + 2 < ce)      asm volatile("cp.async.wait_group 2;");
            else if (c + 1 < ce) asm volatile("cp.async.wait_group 1;");
            else                 asm volatile("cp.async.wait_group 0;");
            __syncthreads();
            if (c + 3 < ce) issue_chunk(layer, c + 3);
            unsigned cur = ab_base + (unsigned)(c & 3) * STAGE_BYTES;
            const int kti = ktbase + c * 4 + kq;
            unsigned a0[4], a1[4];
            ldmA_sw(a0, cur, mh * 32,      kq * 16, lane);
            ldmA_sw(a1, cur, mh * 32 + 16, kq * 16, lane);
#pragma unroll
            for (int gt = 0; gt < 4; gt++) {
                uint2 bb = Wsm[(gt * NKT + kti) * 32 + lane];
                mma16h(acc[0][gt], a0, (const unsigned*)&bb);
                mma16h(acc[1][gt], a1, (const unsigned*)&bb);
            }
        }
    };

    auto waitf = [&](unsigned* flag, unsigned v) {
        if (tid == 0) {
            unsigned f;
            do {
                asm volatile("ld.global.acquire.gpu.u32 %0, [%1];"
                             : "=r"(f) : "l"(flag) : "memory");
            } while (f < v);
        }
        __syncthreads();
    };
    auto arrive = [&](unsigned* cnt, unsigned* flag, unsigned v) {
        __syncthreads();
        if (tid == 0) {
            __threadfence();
            if (atomicAdd(cnt, 1u) == v * NBLK - 1u)
                asm volatile("st.global.release.gpu.u32 [%0], %1;"
                             :: "l"(flag), "r"(v) : "memory");
        }
    };

    for (int t = 0; t < TT; ++t) {
        const int pp = t & 1;
        h0r = g_h0[pp]; h0w = g_h0[pp ^ 1];
        h1r = g_h1[pp]; h1w = g_h1[pp ^ 1];

        // prefetch Gpre operands for this step's layer-0 epilogue
        float pre0[4], pre1[4];
        {
            const float* gp = g_Gpre + (size_t)t * BQ * NG;
#pragma unroll
            for (int g = 0; g < 4; g++) {
                pre0[g] = gp[(size_t)b0 * NG + g * HU + u];
                pre1[g] = gp[(size_t)b1 * NG + g * HU + u];
            }
        }

        // ================= layer 0 =================
#pragma unroll
        for (int i = 0; i < 2; i++)
#pragma unroll
            for (int j = 0; j < 4; j++)
#pragma unroll
                for (int k = 0; k < 4; k++) acc[i][j][k] = 0.f;
        gemm_range(0, 0, 16);

        {   // epilogue L0
            __syncthreads();
            const int p   = kq & 1;
            const int row = mh * 32 + (lane >> 2);
            const int cb2 = 2 * (lane & 3);
            if (kq < 2) {
#pragma unroll
                for (int mt = 0; mt < 2; mt++)
#pragma unroll
                    for (int gt = 0; gt < 4; gt++) {
                        float* base = &gsm[(p * 4 + gt) * 512 + (row + mt * 16) * 8 + cb2];
                        *(float2*)base        = make_float2(acc[mt][gt][0], acc[mt][gt][1]);
                        *(float2*)(base + 64) = make_float2(acc[mt][gt][2], acc[mt][gt][3]);
                    }
            }
            __syncthreads();
            if (kq >= 2) {
#pragma unroll
                for (int mt = 0; mt < 2; mt++)
#pragma unroll
                    for (int gt = 0; gt < 4; gt++) {
                        float* base = &gsm[(p * 4 + gt) * 512 + (row + mt * 16) * 8 + cb2];
                        float2 v0 = *(float2*)base;
                        float2 v1 = *(float2*)(base + 64);
                        v0.x += acc[mt][gt][0]; v0.y += acc[mt][gt][1];
                        v1.x += acc[mt][gt][2]; v1.y += acc[mt][gt][3];
                        *(float2*)base        = v0;
                        *(float2*)(base + 64) = v1;
                    }
            }
            __syncthreads();
#pragma unroll
            for (int r = 0; r < 2; ++r) {
                const int b = r ? b1 : b0;
                const float* pre = r ? pre1 : pre0;
                float gi = gsm[0 * 512 + b * 8 + uu] + gsm[4 * 512 + b * 8 + uu] + pre[0];
                float gf = gsm[1 * 512 + b * 8 + uu] + gsm[5 * 512 + b * 8 + uu] + pre[1];
                float gg = gsm[2 * 512 + b * 8 + uu] + gsm[6 * 512 + b * 8 + uu] + pre[2];
                float go = gsm[3 * 512 + b * 8 + uu] + gsm[7 * 512 + b * 8 + uu] + pre[3];
                float cv = fsig(gf) * cr[0][r] + fsig(gi) * ftanh(gg);
                cr[0][r] = cv;
                h0w[b * HU + u] = __float2half_rn(fsig(go) * ftanh(cv));
            }
        }
        arrive(&g_cntA, &g_flagA, (unsigned)t + 1u);   // includes __syncthreads

        // ================= layer 1 =================
#pragma unroll
        for (int i = 0; i < 2; i++)
#pragma unroll
            for (int j = 0; j < 4; j++)
#pragma unroll
                for (int k = 0; k < 4; k++) acc[i][j][k] = 0.f;

        if (t > 0) waitf(&g_flagB, (unsigned)t);       // h1r final
        gemm_range(1, 16, 32);                          // h1r half (overlaps barrier A)
        waitf(&g_flagA, (unsigned)t + 1u);              // h0w ready from all blocks
        gemm_range(1, 0, 16);                           // h0w half

        {   // epilogue L1
            __syncthreads();
            const int p   = kq & 1;
            const int row = mh * 32 + (lane >> 2);
            const int cb2 = 2 * (lane & 3);
            if (kq < 2) {
#pragma unroll
                for (int mt = 0; mt < 2; mt++)
#pragma unroll
                    for (int gt = 0; gt < 4; gt++) {
                        float* base = &gsm[(p * 4 + gt) * 512 + (row + mt * 16) * 8 + cb2];
                        *(float2*)base        = make_float2(acc[mt][gt][0], acc[mt][gt][1]);
                        *(float2*)(base + 64) = make_float2(acc[mt][gt][2], acc[mt][gt][3]);
                    }
            }
            __syncthreads();
            if (kq >= 2) {
#pragma unroll
                for (int mt = 0; mt < 2; mt++)
#pragma unroll
                    for (int gt = 0; gt < 4; gt++) {
                        float* base = &gsm[(p * 4 + gt) * 512 + (row + mt * 16) * 8 + cb2];
                        float2 v0 = *(float2*)base;
                        float2 v1 = *(float2*)(base + 64);
                        v0.x += acc[mt][gt][0]; v0.y += acc[mt][gt][1];
                        v1.x += acc[mt][gt][2]; v1.y += acc[mt][gt][3];
                        *(float2*)base        = v0;
                        *(float2*)(base + 64) = v1;
                    }
            }
            __syncthreads();
#pragma unroll
            for (int r = 0; r < 2; ++r) {
                const int b = r ? b1 : b0;
                float gi = gsm[0 * 512 + b * 8 + uu] + gsm[4 * 512 + b * 8 + uu] + bsum[uu];
                float gf = gsm[1 * 512 + b * 8 + uu] + gsm[5 * 512 + b * 8 + uu] + bsum[8 + uu];
                float gg = gsm[2 * 512 + b * 8 + uu] + gsm[6 * 512 + b * 8 + uu] + bsum[16 + uu];
                float go = gsm[3 * 512 + b * 8 + uu] + gsm[7 * 512 + b * 8 + uu] + bsum[24 + uu];
                float cv = fsig(gf) * cr[1][r] + fsig(gi) * ftanh(gg);
                cr[1][r] = cv;
                float hv = fsig(go) * ftanh(cv);
                h1w[b * HU + u] = __float2half_rn(hv);
                out[((size_t)b * TT + t) * HU + u] = hv;
            }
        }
        if (t + 1 < TT) arrive(&g_cntB, &g_flagB, (unsigned)t + 1u);
        else            __syncthreads();
    }
}

// ---------------------------------------------------------------------------
extern "C" void kernel_launch(void* const* d_in, const int* in_sizes, int n_in,
                              void* d_out, int out_size) {
    const int*   y     = (const int*)  d_in[0];
    const float* embed = (const float*)d_in[1];
    const float* Wih0  = (const float*)d_in[2];
    const float* Whh0  = (const float*)d_in[3];
    const float* bih0  = (const float*)d_in[4];
    const float* bhh0  = (const float*)d_in[5];
    const float* Wih1  = (const float*)d_in[6];
    const float* Whh1  = (const float*)d_in[7];
    const float* bih1  = (const float*)d_in[8];
    const float* bhh1  = (const float*)d_in[9];
    float* out = (float*)d_out;

    cudaFuncSetAttribute(lstm_persistent,
                         cudaFuncAttributeMaxDynamicSharedMemorySize, SMEM_TOTAL);

    zero_kernel<<<(BQ * HU / 2 + 255) / 256, 256>>>();
    conv_embed<<<(10000 * HD / 4 + 255) / 256, 256>>>(embed);
    pack_w0<<<((NG / 8) * 32 * 32 + 255) / 256, 256>>>(Wih0);
    prep_weights<<<NBLK, 256>>>(Whh0, Wih1, Whh1);
    precompute_kernel<<<dim3(NG / 128, TT / 2), 256>>>(y, bih0, bhh0);
    lstm_persistent<<<NBLK, 256, SMEM_TOTAL>>>(bih1, bhh1, out);

    (void)in_sizes; (void)n_in; (void)out_size;
}